// round 14
// baseline (speedup 1.0000x reference)
#include <cuda_runtime.h>
#include <math.h>

// Problem constants (fixed by reference setup_inputs)
#define N_LG   200000      // line-graph nodes = E_G
#define E_LG   2000000     // line-graph edges
#define E_G    200000
#define D      128         // 2*D_IN = D_H = 128
#define NW     6250        // (N_LG+31)/32 mask words
#define NWS    6252        // smem mask words, padded to /4

// Capacities: expected |S1|~11, |L1|~10, |ND|~130 (Poisson); huge margins
#define S1CAP  512
#define SS1CAP 128         // smem S1 list for slot search
#define L1CAP  2048
#define NDCAP  4096
#define ECAP   192         // per-slot edge list capacity

#define NB 148             // 1 block/SM, guaranteed co-resident
#define NT 1024
#define NTHREADS (NB*NT)   // 151552
#define NI4 (E_LG/4)       // 500000 int4 column loads
#define CHUNK 4            // ceil(NI4 / NTHREADS)
#define FPAD 32            // flag padding: 32 words = 128B per block

// ---------------- device scratch (module-static, zero-initialized) --------
// Entry invariant (restored each run): masks == 0, counters == 0.
__device__ int      g_deg[N_LG];
__device__ unsigned g_need[NW + 1];         // dedup only (S1 alloc)
__device__ unsigned g_needdeg[NW + 1];      // dedup only (degree set)
__device__ int      g_s1[S1CAP];
__device__ int      g_l1[L1CAP];
__device__ int      g_ndlist[NDCAP];        // compact degree-needed node list
__device__ int      g_escnt[S1CAP];         // per-slot edge counts
__device__ int      g_es[S1CAP * ECAP];     // per-slot source lists
__device__ float    g_z[D];                 // atomically accumulated layer-1 output
__device__ int      g_n1, g_l1cnt, g_ndcnt;
__device__ int      g_done;                 // worker publication count
__device__ float    g_sink;                 // prefetch DCE blocker

// flag-array barrier state (monotonic across replays; zero-initialized)
// one flag per 128B line: no LTS write serialization across blocks
__device__ volatile unsigned g_flagsA[NB * FPAD];  // arrivals
__device__ volatile unsigned g_flagsR[NB * FPAD];  // per-block releases

__global__ void __launch_bounds__(NT, 1)
fused_kernel(const float* __restrict__ x,      // [20000,64]
             const int*   __restrict__ gei,    // [2,200000]
             const int*   __restrict__ lg,     // [2,2000000]
             const int*   __restrict__ idx01,  // [1]
             const float* __restrict__ W0, const float* __restrict__ b0,
             const float* __restrict__ W1, const float* __restrict__ b1,
             const float* __restrict__ Wl, const float* __restrict__ bl,
             float* __restrict__ out) {
    __shared__ unsigned smask[NWS];            // 25 KB local membership mask
    __shared__ int      ss1[SS1CAP];           // S1 node list (slot search)
    __shared__ float    ysh[D];                // per-slot y accumulator
    __shared__ float    pacc[8][D];            // k-split partials
    __shared__ float    zsh[D];
    __shared__ int      scoef_cnt;
    __shared__ int      sfin;
    __shared__ unsigned sbase;

    const int tid = blockIdx.x * blockDim.x + threadIdx.x;
    const int t = __ldg(idx01);
    const int4* __restrict__ col4 = (const int4*)(lg + E_LG);
    const int*  __restrict__ row  = lg;

    // barrier generation base for this replay (persists via flagsR)
    if (threadIdx.x == 0) { sbase = g_flagsR[blockIdx.x * FPAD]; sfin = 0; }
    __syncthreads();                    // publish sbase to ALL threads

    // symmetric flag-array barrier: padded arrival + per-block release flags
    auto gsync = [&](unsigned g) {
        __syncthreads();
        if (threadIdx.x == 0) { __threadfence(); g_flagsA[blockIdx.x * FPAD] = g; }
        if (blockIdx.x == 0) {
            if (threadIdx.x < NB) {
                while (g_flagsA[threadIdx.x * FPAD] < g) { }
                __threadfence();
            }
            __syncthreads();
            if (threadIdx.x < NB) g_flagsR[threadIdx.x * FPAD] = g;  // parallel release
        } else {
            if (threadIdx.x == 0) {
                while (g_flagsR[blockIdx.x * FPAD] < g) { }          // own line
                __threadfence();
            }
            __syncthreads();
        }
    };

    // Preload this thread's scan chunk ONCE.
    int4 v[CHUNK];
    #pragma unroll
    for (int u = 0; u < CHUNK; u++) {
        int id = tid + u * NTHREADS;
        v[u] = (id < NI4) ? col4[id] : make_int4(-1, -1, -1, -1);
    }

    // zero smem mask NOW (overlaps P1 scan; used first in P2)
    {
        uint4* sm4 = (uint4*)smask;
        for (int i = threadIdx.x; i < NWS / 4; i += NT) sm4[i] = make_uint4(0, 0, 0, 0);
    }

    // ---- P1: find edges into t; allocate S1 slots inline --------------------
    auto alloc_slot = [&](int node) {
        unsigned b = 1u << (node & 31);
        unsigned old = atomicOr(&g_need[node >> 5], b);
        if (!(old & b)) {
            int s = atomicAdd(&g_n1, 1);
            if (s < S1CAP) { g_s1[s] = node; g_escnt[s] = 0; }
            unsigned od = atomicOr(&g_needdeg[node >> 5], b);
            if (!(od & b)) {
                int p = atomicAdd(&g_ndcnt, 1);
                if (p < NDCAP) g_ndlist[p] = node;
                g_deg[node] = 0;
            }
        }
    };
    if (tid == 0) alloc_slot(t);
    if (tid < D) g_z[tid] = 0.f;        // zero z for this replay (<< B3)
    #pragma unroll
    for (int u = 0; u < CHUNK; u++) {
        int cs[4] = {v[u].x, v[u].y, v[u].z, v[u].w};
        #pragma unroll
        for (int k = 0; k < 4; k++) {
            if (cs[k] == t) {
                int r = __ldg(&row[(tid + u * NTHREADS) * 4 + k]);
                int p = atomicAdd(&g_l1cnt, 1);
                if (p < L1CAP) g_l1[p] = r;
                alloc_slot(r);
            }
        }
    }
    // weight prefetch into L2, one element per thread (fully overlapped)
    {
        float w = 0.f;
        if (tid < D * D)              w = __ldg(&W0[tid]);
        else if (tid < 2 * D * D)     w = __ldg(&W1[tid - D * D]);
        else if (tid < 2 * D * D + D) w = __ldg(&b0[tid - 2 * D * D]) +
                                          __ldg(&b1[tid - 2 * D * D]) +
                                          __ldg(&Wl[tid - 2 * D * D]);
        if (w == 12345.678f) g_sink = w;   // unprovable: keeps loads alive
    }
    gsync(sbase + 1);   // B1

    const int n1 = min(g_n1, S1CAP);

    // ---- P2: build local S1 mask (pre-zeroed); collect per-slot edge lists --
    for (int i = threadIdx.x; i < n1; i += NT) {
        int node = g_s1[i];
        if (i < SS1CAP) ss1[i] = node;
        atomicOr(&smask[node >> 5], 1u << (node & 31));
    }
    __syncthreads();
    #pragma unroll
    for (int u = 0; u < CHUNK; u++) {
        int cs[4] = {v[u].x, v[u].y, v[u].z, v[u].w};
        #pragma unroll
        for (int k = 0; k < 4; k++) {
            int c = cs[k];
            if (c >= 0 && ((smask[c >> 5] >> (c & 31)) & 1)) {
                int r = __ldg(&row[(tid + u * NTHREADS) * 4 + k]);
                int s = 0;
                int nss = min(n1, SS1CAP);
                for (int q = 0; q < nss; q++) if (ss1[q] == c) s = q;
                int p = atomicAdd(&g_escnt[s], 1);
                if (p < ECAP) g_es[s * ECAP + p] = r;
                unsigned b = 1u << (r & 31);
                unsigned old = atomicOr(&g_needdeg[r >> 5], b);
                if (!(old & b)) {
                    int q2 = atomicAdd(&g_ndcnt, 1);
                    if (q2 < NDCAP) g_ndlist[q2] = r;
                    g_deg[r] = 0;
                }
            }
        }
    }
    gsync(sbase + 2);   // B2

    const int ndc = min(g_ndcnt, NDCAP);
    const int l1 = min(g_l1cnt, L1CAP);
    const int W = min(n1, NB);
    const int grp = threadIdx.x >> 4, l16 = threadIdx.x & 15;

    // ---- worker index prefetch (overlaps P3): edge sources + gei endpoints --
    int pr = -1, ps0 = 0, ps1 = 0, myc = 0, pcnt = 0;
    if ((int)blockIdx.x < W) {
        const int j0 = blockIdx.x;
        pcnt = min(g_escnt[j0], ECAP);
        const int node0 = (j0 < SS1CAP) ? ss1[j0] : g_s1[j0];
        if (grp <= pcnt) {
            pr = (grp < pcnt) ? g_es[j0 * ECAP + grp] : node0;   // ==pcnt: self-loop
            ps0 = __ldg(&gei[pr]);
            ps1 = __ldg(&gei[E_G + pr]);
        }
        for (int i = threadIdx.x; i < l1; i += NT) if (g_l1[i] == node0) myc++;
    }

    // ---- P3: OR ND bits into existing mask (S1 bits already set); count -----
    for (int i = threadIdx.x; i < ndc; i += NT) {
        int node = g_ndlist[i];
        atomicOr(&smask[node >> 5], 1u << (node & 31));
    }
    __syncthreads();
    #pragma unroll
    for (int u = 0; u < CHUNK; u++) {
        int cs[4] = {v[u].x, v[u].y, v[u].z, v[u].w};
        #pragma unroll
        for (int k = 0; k < 4; k++) {
            int c = cs[k];
            if (c >= 0 && ((smask[c >> 5] >> (c & 31)) & 1)) atomicAdd(&g_deg[c], 1);
        }
    }
    gsync(sbase + 3);   // B3 (last barrier)

    if ((int)blockIdx.x >= W) {
        // non-workers: restore entry invariant (idempotent), then exit
        for (int i = threadIdx.x; i < ndc; i += NT) g_needdeg[g_ndlist[i] >> 5] = 0u;
        for (int i = threadIdx.x; i < n1; i += NT)  g_need[g_s1[i] >> 5] = 0u;
        return;
    }

    // ===== WORKERS: one slot per block (strided if n1 > NB) ===================
    const float dinv_t = rsqrtf((float)(g_deg[t] + 1));
    const int j0 = blockIdx.x;

    for (int j = j0; j < n1; j += W) {
        const int node = (j < SS1CAP) ? ss1[j] : g_s1[j];
        const int cnt = (j == j0) ? pcnt : min(g_escnt[j], ECAP);
        const float dinv_j = rsqrtf((float)(g_deg[node] + 1));

        if (threadIdx.x < D) ysh[threadIdx.x] = 0.f;
        if (threadIdx.x == 0) scoef_cnt = 0;
        __syncthreads();
        if (j == j0) { if (myc) atomicAdd(&scoef_cnt, myc); }
        else for (int i = threadIdx.x; i < l1; i += NT)
                 if (g_l1[i] == node) atomicAdd(&scoef_cnt, 1);

        // y_j accumulation: 16-lane group per edge; i == cnt is self-loop
        for (int i = grp; i <= cnt; i += NT / 16) {
            int r, s0, s1_;
            if (j == j0 && i == grp) { r = pr; s0 = ps0; s1_ = ps1; }   // prefetched
            else {
                r = (i < cnt) ? g_es[j * ECAP + i] : node;
                s0 = __ldg(&gei[r]); s1_ = __ldg(&gei[E_G + r]);
            }
            // deg and x loads issue in parallel (both depend only on r / s0,s1_)
            float w = (i < cnt) ? rsqrtf((float)(g_deg[r] + 1)) * dinv_j
                                : dinv_j * dinv_j;
            const float4 f0 = *((const float4*)(x + s0 * 64) + l16);
            const float4 f1 = *((const float4*)(x + s1_ * 64) + l16);
            int d = l16 * 4;
            atomicAdd(&ysh[d + 0], w * f0.x);
            atomicAdd(&ysh[d + 1], w * f0.y);
            atomicAdd(&ysh[d + 2], w * f0.z);
            atomicAdd(&ysh[d + 3], w * f0.w);
            atomicAdd(&ysh[64 + d + 0], w * f1.x);
            atomicAdd(&ysh[64 + d + 1], w * f1.y);
            atomicAdd(&ysh[64 + d + 2], w * f1.z);
            atomicAdd(&ysh[64 + d + 3], w * f1.w);
        }
        __syncthreads();

        // z += coef_j * relu(y_j @ W0 + b0), 8-way k-split, direct atomic accum
        const float coef = (float)scoef_cnt * dinv_j * dinv_t +
                           ((node == t) ? dinv_t * dinv_t : 0.f);
        const int part = threadIdx.x >> 7;       // 0..7
        const int d = threadIdx.x & (D - 1);     // 0..127
        float acc = 0.f;
        const int k0 = part * 16;
        #pragma unroll
        for (int k = 0; k < 16; k++)
            acc = fmaf(ysh[k0 + k], W0[(k0 + k) * D + d], acc);
        pacc[part][d] = acc;
        __syncthreads();
        if (part == 0) {
            float a = b0[d];
            #pragma unroll
            for (int p = 0; p < 8; p++) a += pacc[p][d];
            atomicAdd(&g_z[d], coef * fmaxf(a, 0.f));   // direct, no h1 roundtrip
        }
        __syncthreads();
        if (threadIdx.x == 0) {
            __threadfence();
            int p = atomicAdd(&g_done, 1);       // publish slot j
            if (p == n1 - 1) sfin = 1;           // last publisher finishes
        }
        __syncthreads();
    }

    // ===== FINISHER: the block that published last ============================
    if (sfin) {
        if (threadIdx.x == 0) __threadfence();   // acquire all z adds
        __syncthreads();

        const int part = threadIdx.x >> 7;       // 0..7
        const int d = threadIdx.x & (D - 1);
        if (part == 0) zsh[d] = g_z[d];          // single 128-float L2 read
        __syncthreads();

        float acc = 0.f;
        const int k0 = part * 16;
        #pragma unroll
        for (int k = 0; k < 16; k++)
            acc = fmaf(zsh[k0 + k], W1[(k0 + k) * D + d], acc);
        pacc[part][d] = acc;
        __syncthreads();
        if (part == 0) {
            float a = b1[d];
            #pragma unroll
            for (int p = 0; p < 8; p++) a += pacc[p][d];
            pacc[0][d] = fmaxf(a, 0.f) * Wl[d];
        }
        __syncthreads();
        for (int off = 64; off > 0; off >>= 1) {
            if (threadIdx.x < off) pacc[0][threadIdx.x] += pacc[0][threadIdx.x + off];
            __syncthreads();
        }
        if (threadIdx.x == 0) {
            out[0] = 1.f / (1.f + expf(-(pacc[0][0] + bl[0])));
            g_done = 0; g_n1 = 0; g_l1cnt = 0; g_ndcnt = 0;  // restore invariant
        }
        // safety: if every block was a worker, restore masks here too
        if (W == NB) {
            for (int i = threadIdx.x; i < ndc; i += NT) g_needdeg[g_ndlist[i] >> 5] = 0u;
            for (int i = threadIdx.x; i < n1; i += NT)  g_need[g_s1[i] >> 5] = 0u;
        }
    }
}

extern "C" void kernel_launch(void* const* d_in, const int* in_sizes, int n_in,
                              void* d_out, int out_size) {
    const float* x     = (const float*)d_in[0];
    const int*   gei   = (const int*)  d_in[1];
    const int*   lg    = (const int*)  d_in[2];
    const int*   idx01 = (const int*)  d_in[3];
    const float* W0    = (const float*)d_in[4];
    const float* b0    = (const float*)d_in[5];
    const float* W1    = (const float*)d_in[6];
    const float* b1    = (const float*)d_in[7];
    const float* Wl    = (const float*)d_in[8];
    const float* bl    = (const float*)d_in[9];
    float* out = (float*)d_out;

    fused_kernel<<<NB, NT>>>(x, gei, lg, idx01, W0, b0, W1, b1, Wl, bl, out);
}

// round 15
// speedup vs baseline: 1.1545x; 1.1545x over previous
#include <cuda_runtime.h>
#include <math.h>

// Problem constants (fixed by reference setup_inputs)
#define N_LG   200000      // line-graph nodes = E_G
#define E_LG   2000000     // line-graph edges
#define E_G    200000
#define D      128         // 2*D_IN = D_H = 128
#define NW     6250        // (N_LG+31)/32 mask words
#define NWS    6252        // smem mask words, padded to /4

// Capacities: expected |S1|~11, |L1|~10, |ND|~130 (Poisson); huge margins
#define S1CAP  512
#define SS1CAP 128         // smem S1 list for slot search
#define L1CAP  2048
#define NDCAP  4096
#define ECAP   192         // per-slot edge list capacity

#define NB 148             // 1 block/SM, guaranteed co-resident
#define NT 1024
#define NTHREADS (NB*NT)   // 151552
#define NI4 (E_LG/4)       // 500000 int4 column loads
#define CHUNK 4            // ceil(NI4 / NTHREADS)

// ---------------- device scratch (module-static, zero-initialized) --------
// Entry invariant (restored each run): masks == 0, counters == 0.
__device__ int      g_deg[N_LG];
__device__ unsigned g_need[NW + 1];         // dedup only (S1 alloc)
__device__ unsigned g_needdeg[NW + 1];      // dedup only (degree set)
__device__ int      g_s1[S1CAP];
__device__ int      g_l1[L1CAP];
__device__ int      g_ndlist[NDCAP];        // compact degree-needed node list
__device__ int      g_escnt[S1CAP];         // per-slot edge counts
__device__ int      g_es[S1CAP * ECAP];     // per-slot source lists
__device__ float    g_z[D];                 // atomically accumulated layer-1 output
__device__ int      g_n1, g_l1cnt, g_ndcnt;
__device__ int      g_done;                 // worker publication count
__device__ float    g_sink;                 // prefetch DCE blocker

// single-counter barrier: monotonic across replays; epoch gives each replay
// its own counter window (incremented by the finisher; kernel-boundary visible)
__device__ int          g_epoch;
__device__ volatile int g_bcnt;

__global__ void __launch_bounds__(NT, 1)
fused_kernel(const float* __restrict__ x,      // [20000,64]
             const int*   __restrict__ gei,    // [2,200000]
             const int*   __restrict__ lg,     // [2,2000000]
             const int*   __restrict__ idx01,  // [1]
             const float* __restrict__ W0, const float* __restrict__ b0,
             const float* __restrict__ W1, const float* __restrict__ b1,
             const float* __restrict__ Wl, const float* __restrict__ bl,
             float* __restrict__ out) {
    __shared__ unsigned smask[NWS];            // 25 KB local membership mask
    __shared__ int      ss1[SS1CAP];           // S1 node list (slot search)
    __shared__ float    ysh[D];                // per-slot y accumulator
    __shared__ float    pacc[8][D];            // k-split partials
    __shared__ float    zsh[D];
    __shared__ int      scoef_cnt;
    __shared__ int      sfin;
    __shared__ int      sepoch;

    const int tid = blockIdx.x * blockDim.x + threadIdx.x;
    const int t = __ldg(idx01);
    const int4* __restrict__ col4 = (const int4*)(lg + E_LG);
    const int*  __restrict__ row  = lg;

    if (threadIdx.x == 0) { sepoch = g_epoch; sfin = 0; }
    __syncthreads();                    // publish sepoch to ALL threads
    const int bbase = sepoch * 3 * NB;  // this replay's counter window

    // one-hop barrier: arrive via atomicAdd, detect by polling the counter
    auto gsync = [&](int k) {           // k = 1,2,3
        __syncthreads();
        if (threadIdx.x == 0) {
            __threadfence();
            atomicAdd((int*)&g_bcnt, 1);
            const int tgt = bbase + k * NB;
            while (g_bcnt < tgt) { }
            __threadfence();
        }
        __syncthreads();
    };

    // Preload this thread's scan chunk ONCE.
    int4 v[CHUNK];
    #pragma unroll
    for (int u = 0; u < CHUNK; u++) {
        int id = tid + u * NTHREADS;
        v[u] = (id < NI4) ? col4[id] : make_int4(-1, -1, -1, -1);
    }

    // ---- P1: find edges into t; allocate S1 slots inline --------------------
    auto alloc_slot = [&](int node) {
        unsigned b = 1u << (node & 31);
        unsigned old = atomicOr(&g_need[node >> 5], b);
        if (!(old & b)) {
            int s = atomicAdd(&g_n1, 1);
            if (s < S1CAP) { g_s1[s] = node; g_escnt[s] = 0; }
            unsigned od = atomicOr(&g_needdeg[node >> 5], b);
            if (!(od & b)) {
                int p = atomicAdd(&g_ndcnt, 1);
                if (p < NDCAP) g_ndlist[p] = node;
                g_deg[node] = 0;
            }
        }
    };
    if (tid == 0) alloc_slot(t);
    if (tid < D) g_z[tid] = 0.f;        // zero z for this replay (<< B3)
    #pragma unroll
    for (int u = 0; u < CHUNK; u++) {
        int cs[4] = {v[u].x, v[u].y, v[u].z, v[u].w};
        #pragma unroll
        for (int k = 0; k < 4; k++) {
            if (cs[k] == t) {
                int r = __ldg(&row[(tid + u * NTHREADS) * 4 + k]);
                int p = atomicAdd(&g_l1cnt, 1);
                if (p < L1CAP) g_l1[p] = r;
                alloc_slot(r);
            }
        }
    }
    // weight prefetch into L2, one element per thread (fully overlapped)
    {
        float w = 0.f;
        if (tid < D * D)              w = __ldg(&W0[tid]);
        else if (tid < 2 * D * D)     w = __ldg(&W1[tid - D * D]);
        else if (tid < 2 * D * D + D) w = __ldg(&b0[tid - 2 * D * D]) +
                                          __ldg(&b1[tid - 2 * D * D]) +
                                          __ldg(&Wl[tid - 2 * D * D]);
        if (w == 12345.678f) g_sink = w;   // unprovable: keeps loads alive
    }
    gsync(1);   // B1

    const int n1 = min(g_n1, S1CAP);

    // ---- P2: build local S1 mask; collect per-slot edge lists ---------------
    {
        uint4* sm4 = (uint4*)smask;
        for (int i = threadIdx.x; i < NWS / 4; i += NT) sm4[i] = make_uint4(0, 0, 0, 0);
        __syncthreads();
        for (int i = threadIdx.x; i < n1; i += NT) {
            int node = g_s1[i];
            if (i < SS1CAP) ss1[i] = node;
            atomicOr(&smask[node >> 5], 1u << (node & 31));
        }
        __syncthreads();
    }
    #pragma unroll
    for (int u = 0; u < CHUNK; u++) {
        int cs[4] = {v[u].x, v[u].y, v[u].z, v[u].w};
        #pragma unroll
        for (int k = 0; k < 4; k++) {
            int c = cs[k];
            if (c >= 0 && ((smask[c >> 5] >> (c & 31)) & 1)) {
                int r = __ldg(&row[(tid + u * NTHREADS) * 4 + k]);
                int s = 0;
                int nss = min(n1, SS1CAP);
                for (int q = 0; q < nss; q++) if (ss1[q] == c) s = q;
                int p = atomicAdd(&g_escnt[s], 1);
                if (p < ECAP) g_es[s * ECAP + p] = r;
                unsigned b = 1u << (r & 31);
                unsigned old = atomicOr(&g_needdeg[r >> 5], b);
                if (!(old & b)) {
                    int q2 = atomicAdd(&g_ndcnt, 1);
                    if (q2 < NDCAP) g_ndlist[q2] = r;
                    g_deg[r] = 0;
                }
            }
        }
    }
    gsync(2);   // B2

    const int ndc = min(g_ndcnt, NDCAP);
    const int l1 = min(g_l1cnt, L1CAP);

    // ---- P3: OR ND bits into existing mask (S1 bits already set); count -----
    for (int i = threadIdx.x; i < ndc; i += NT) {
        int node = g_ndlist[i];
        atomicOr(&smask[node >> 5], 1u << (node & 31));
    }
    __syncthreads();
    #pragma unroll
    for (int u = 0; u < CHUNK; u++) {
        int cs[4] = {v[u].x, v[u].y, v[u].z, v[u].w};
        #pragma unroll
        for (int k = 0; k < 4; k++) {
            int c = cs[k];
            if (c >= 0 && ((smask[c >> 5] >> (c & 31)) & 1)) atomicAdd(&g_deg[c], 1);
        }
    }
    gsync(3);   // B3 (last barrier)

    const int W = min(n1, NB);

    if ((int)blockIdx.x >= W) {
        // non-workers: restore entry invariant (idempotent), then exit
        for (int i = threadIdx.x; i < ndc; i += NT) g_needdeg[g_ndlist[i] >> 5] = 0u;
        for (int i = threadIdx.x; i < n1; i += NT)  g_need[g_s1[i] >> 5] = 0u;
        return;
    }

    // ===== WORKERS: one slot per block (strided if n1 > NB) ===================
    const float dinv_t = rsqrtf((float)(g_deg[t] + 1));
    const int grp = threadIdx.x >> 4, l16 = threadIdx.x & 15;

    for (int j = blockIdx.x; j < n1; j += W) {
        const int node = (j < SS1CAP) ? ss1[j] : g_s1[j];   // smem, no L2 hop
        const int cnt = min(g_escnt[j], ECAP);
        const float dinv_j = rsqrtf((float)(g_deg[node] + 1));

        if (threadIdx.x < D) ysh[threadIdx.x] = 0.f;
        if (threadIdx.x == 0) scoef_cnt = 0;
        __syncthreads();
        for (int i = threadIdx.x; i < l1; i += NT)
            if (g_l1[i] == node) atomicAdd(&scoef_cnt, 1);

        // y_j accumulation: 16-lane group per edge; i == cnt is self-loop
        for (int i = grp; i <= cnt; i += NT / 16) {
            int r; float w;
            if (i < cnt) { r = g_es[j * ECAP + i];
                           w = rsqrtf((float)(g_deg[r] + 1)) * dinv_j; }
            else         { r = node; w = dinv_j * dinv_j; }
            int s0 = __ldg(&gei[r]), s1_ = __ldg(&gei[E_G + r]);
            const float4 f0 = *((const float4*)(x + s0 * 64) + l16);
            const float4 f1 = *((const float4*)(x + s1_ * 64) + l16);
            int d = l16 * 4;
            atomicAdd(&ysh[d + 0], w * f0.x);
            atomicAdd(&ysh[d + 1], w * f0.y);
            atomicAdd(&ysh[d + 2], w * f0.z);
            atomicAdd(&ysh[d + 3], w * f0.w);
            atomicAdd(&ysh[64 + d + 0], w * f1.x);
            atomicAdd(&ysh[64 + d + 1], w * f1.y);
            atomicAdd(&ysh[64 + d + 2], w * f1.z);
            atomicAdd(&ysh[64 + d + 3], w * f1.w);
        }
        __syncthreads();

        // z += coef_j * relu(y_j @ W0 + b0), 8-way k-split, direct atomic accum
        const float coef = (float)scoef_cnt * dinv_j * dinv_t +
                           ((node == t) ? dinv_t * dinv_t : 0.f);
        const int part = threadIdx.x >> 7;       // 0..7
        const int d = threadIdx.x & (D - 1);     // 0..127
        float acc = 0.f;
        const int k0 = part * 16;
        #pragma unroll
        for (int k = 0; k < 16; k++)
            acc = fmaf(ysh[k0 + k], W0[(k0 + k) * D + d], acc);
        pacc[part][d] = acc;
        __syncthreads();
        if (part == 0) {
            float a = b0[d];
            #pragma unroll
            for (int p = 0; p < 8; p++) a += pacc[p][d];
            atomicAdd(&g_z[d], coef * fmaxf(a, 0.f));   // direct, no h1 roundtrip
        }
        __syncthreads();
        if (threadIdx.x == 0) {
            __threadfence();
            int p = atomicAdd(&g_done, 1);       // publish slot j
            if (p == n1 - 1) sfin = 1;           // last publisher finishes
        }
        __syncthreads();
    }

    // ===== FINISHER: the block that published last ============================
    if (sfin) {
        if (threadIdx.x == 0) __threadfence();   // acquire all z adds
        __syncthreads();

        const int part = threadIdx.x >> 7;       // 0..7
        const int d = threadIdx.x & (D - 1);
        if (part == 0) zsh[d] = g_z[d];          // single 128-float L2 read
        __syncthreads();

        float acc = 0.f;
        const int k0 = part * 16;
        #pragma unroll
        for (int k = 0; k < 16; k++)
            acc = fmaf(zsh[k0 + k], W1[(k0 + k) * D + d], acc);
        pacc[part][d] = acc;
        __syncthreads();
        if (part == 0) {
            float a = b1[d];
            #pragma unroll
            for (int p = 0; p < 8; p++) a += pacc[p][d];
            pacc[0][d] = fmaxf(a, 0.f) * Wl[d];
        }
        __syncthreads();
        for (int off = 64; off > 0; off >>= 1) {
            if (threadIdx.x < off) pacc[0][threadIdx.x] += pacc[0][threadIdx.x + off];
            __syncthreads();
        }
        if (threadIdx.x == 0) {
            out[0] = 1.f / (1.f + expf(-(pacc[0][0] + bl[0])));
            g_done = 0; g_n1 = 0; g_l1cnt = 0; g_ndcnt = 0;  // restore invariant
            g_epoch = sepoch + 1;                // advance barrier window
        }
        // safety: if every block was a worker, restore masks here too
        if (W == NB) {
            for (int i = threadIdx.x; i < ndc; i += NT) g_needdeg[g_ndlist[i] >> 5] = 0u;
            for (int i = threadIdx.x; i < n1; i += NT)  g_need[g_s1[i] >> 5] = 0u;
        }
    }
}

extern "C" void kernel_launch(void* const* d_in, const int* in_sizes, int n_in,
                              void* d_out, int out_size) {
    const float* x     = (const float*)d_in[0];
    const int*   gei   = (const int*)  d_in[1];
    const int*   lg    = (const int*)  d_in[2];
    const int*   idx01 = (const int*)  d_in[3];
    const float* W0    = (const float*)d_in[4];
    const float* b0    = (const float*)d_in[5];
    const float* W1    = (const float*)d_in[6];
    const float* b1    = (const float*)d_in[7];
    const float* Wl    = (const float*)d_in[8];
    const float* bl    = (const float*)d_in[9];
    float* out = (float*)d_out;

    fused_kernel<<<NB, NT>>>(x, gei, lg, idx01, W0, b0, W1, b1, Wl, bl, out);
}